// round 2
// baseline (speedup 1.0000x reference)
#include <cuda_runtime.h>
#include <math.h>

#define BSZ   64
#define NPTS  4096            // 64*64 points per batch
#define CH    128
#define SM_SL 32              // mean slices per batch
#define SV_SL 32              // var slices per batch
#define EPSV   1e-5f
#define CLAMPV 1e-8f

// ---- static scratch (no runtime allocation allowed) ----
__device__ float g_part_mean[BSZ * SM_SL * CH];   // 1 MB
__device__ float g_mean[BSZ * CH];
__device__ float g_vpart[BSZ * SV_SL];
__device__ float g_scale[BSZ];

__device__ __forceinline__ float wred(float v) {
#pragma unroll
    for (int o = 16; o > 0; o >>= 1)
        v += __shfl_xor_sync(0xffffffffu, v, o);
    return v;
}

// ---------------------------------------------------------------------------
// Kernel A: per-(batch, slice) component-wise partial sums of x.
// thread j accumulates component j over 128 points. Coalesced 128B/warp.
// ---------------------------------------------------------------------------
__global__ void kmean_part(const float* __restrict__ x) {
    const int b = blockIdx.x, s = blockIdx.y;
    const int j = threadIdx.x;                    // 0..127
    const int PPC = NPTS / SM_SL;                 // 128 points
    const float* base = x + ((size_t)b * NPTS + (size_t)s * PPC) * CH + j;
    float acc0 = 0.f, acc1 = 0.f;
#pragma unroll 16
    for (int p = 0; p < PPC; p += 2) {
        acc0 += base[(size_t)p * CH];
        acc1 += base[(size_t)(p + 1) * CH];
    }
    g_part_mean[(b * SM_SL + s) * CH + j] = acc0 + acc1;
}

// ---------------------------------------------------------------------------
// Kernel B: finalize mean -> project onto hyperboloid.
// mean = m / sqrt(max(-linner(m,m), 1e-8)), linner(a,b)=dot(a,b)-2*a0*b0
// ---------------------------------------------------------------------------
__global__ void kmean_fin() {
    const int b = blockIdx.x;
    const int j = threadIdx.x;                    // 0..127
    float m = 0.f;
#pragma unroll
    for (int s = 0; s < SM_SL; s++)
        m += g_part_mean[(b * SM_SL + s) * CH + j];
    m *= (1.0f / (float)NPTS);

    __shared__ float red[CH];
    __shared__ float s_m0, s_inv;
    red[j] = m * m;
    if (j == 0) s_m0 = m;
    __syncthreads();
    for (int off = CH / 2; off > 0; off >>= 1) {
        if (j < off) red[j] += red[j + off];
        __syncthreads();
    }
    if (j == 0) {
        float l = red[0] - 2.0f * s_m0 * s_m0;    // linner(m,m)
        s_inv = 1.0f / sqrtf(fmaxf(-l, CLAMPV));
    }
    __syncthreads();
    g_mean[b * CH + j] = m * s_inv;
}

// ---------------------------------------------------------------------------
// Kernel C: per-(batch, slice) partial sums of ||x_T|| (Frechet variance).
// warp-per-point, float4 per lane (128 ch = 32 lanes * 4).
// ---------------------------------------------------------------------------
__global__ void kvar_part(const float* __restrict__ x) {
    const int b = blockIdx.x, s = blockIdx.y;
    __shared__ float smean[CH];
    __shared__ float wsum[8];
    const int tid = threadIdx.x;                  // 0..255
    if (tid < CH) smean[tid] = g_mean[b * CH + tid];
    __syncthreads();

    const int lane = tid & 31, w = tid >> 5;
    const float m0 = smean[0];
    const float4 mv = ((const float4*)smean)[lane];

    const int PPC = NPTS / SV_SL;                 // 128
    const int PPW = PPC / 8;                      // 16 points per warp
    const int p0 = s * PPC + w * PPW;

    float acc = 0.f;
    for (int p = p0; p < p0 + PPW; p++) {
        const float4 xv = ((const float4*)(x + ((size_t)b * NPTS + p) * CH))[lane];
        float d = xv.x * mv.x + xv.y * mv.y + xv.z * mv.z + xv.w * mv.w;
        d = wred(d);                              // dot(mean, x)
        const float x0 = __shfl_sync(0xffffffffu, xv.x, 0);
        const float alpha = fmaxf(2.0f * m0 * x0 - d, 1.0f + 1e-7f);

        float4 u;
        u.x = xv.x - alpha * mv.x;
        u.y = xv.y - alpha * mv.y;
        u.z = xv.z - alpha * mv.z;
        u.w = xv.w - alpha * mv.w;
        float du = u.x * u.x + u.y * u.y + u.z * u.z + u.w * u.w;
        du = wred(du);
        const float u0 = x0 - alpha * m0;
        const float lu = du - 2.0f * u0 * u0;     // linner(u,u)
        const float un = sqrtf(fmaxf(lu, CLAMPV));
        const float sc = acoshf(alpha) / un;

        const float t0 = sc * u0;
        const float corr = t0 / (1.0f + m0);
        float4 t;
        t.x = sc * u.x - corr * (mv.x + (lane == 0 ? 1.0f : 0.0f));
        t.y = sc * u.y - corr * mv.y;
        t.z = sc * u.z - corr * mv.z;
        t.w = sc * u.w - corr * mv.w;
        float n2 = t.x * t.x + t.y * t.y + t.z * t.z + t.w * t.w;
        n2 = wred(n2);
        acc += sqrtf(n2);
    }
    if (lane == 0) wsum[w] = acc;
    __syncthreads();
    if (tid == 0) {
        float s8 = 0.f;
#pragma unroll
        for (int i = 0; i < 8; i++) s8 += wsum[i];
        g_vpart[b * SV_SL + s] = s8;
    }
}

// ---------------------------------------------------------------------------
// Kernel D: finalize variance -> per-batch scale gamma/(var+eps)
// ---------------------------------------------------------------------------
__global__ void kvar_fin(const float* __restrict__ gamma) {
    const int b = threadIdx.x;                    // 0..63
    float s = 0.f;
#pragma unroll
    for (int i = 0; i < SV_SL; i++) s += g_vpart[b * SV_SL + i];
    const float var = s * (1.0f / (float)NPTS);
    g_scale[b] = gamma[0] / (var + EPSV);
}

// ---------------------------------------------------------------------------
// Kernel E: recompute x_T, scale, transport to beta, expmap, write out.
// warp-per-point; 8 points per CTA; 512 CTAs per batch (never spans batches).
// ---------------------------------------------------------------------------
__global__ void kfinal(const float* __restrict__ x,
                       const float* __restrict__ beta,
                       float* __restrict__ out) {
    const int b = blockIdx.x >> 9;                // 4096/8 = 512 CTAs per batch
    __shared__ float smean[CH];
    __shared__ float sbeta[CH];
    const int tid = threadIdx.x;                  // 0..255
    if (tid < CH) smean[tid] = g_mean[b * CH + tid];
    else          sbeta[tid - CH] = beta[tid - CH];
    __syncthreads();

    const int lane = tid & 31, w = tid >> 5;
    const int pt = blockIdx.x * 8 + w;            // global point id
    const float m0 = smean[0];
    const float b0 = sbeta[0];
    const float g  = g_scale[b];
    const float4 mv = ((const float4*)smean)[lane];
    const float4 bv = ((const float4*)sbeta)[lane];

    const float4 xv = ((const float4*)(x + (size_t)pt * CH))[lane];

    // logmap at mean
    float d = xv.x * mv.x + xv.y * mv.y + xv.z * mv.z + xv.w * mv.w;
    d = wred(d);
    const float x0 = __shfl_sync(0xffffffffu, xv.x, 0);
    const float alpha = fmaxf(2.0f * m0 * x0 - d, 1.0f + 1e-7f);

    float4 u;
    u.x = xv.x - alpha * mv.x;
    u.y = xv.y - alpha * mv.y;
    u.z = xv.z - alpha * mv.z;
    u.w = xv.w - alpha * mv.w;
    float du = u.x * u.x + u.y * u.y + u.z * u.z + u.w * u.w;
    du = wred(du);
    const float u0 = x0 - alpha * m0;
    const float lu = du - 2.0f * u0 * u0;
    const float un = sqrtf(fmaxf(lu, CLAMPV));
    const float sc = acoshf(alpha) / un;

    // transport mean -> origin, then scale by gamma/(var+eps)
    const float t0p = sc * u0;
    const float corr = t0p / (1.0f + m0);
    float4 t;
    t.x = (sc * u.x - corr * (mv.x + (lane == 0 ? 1.0f : 0.0f))) * g;
    t.y = (sc * u.y - corr * mv.y) * g;
    t.z = (sc * u.z - corr * mv.z) * g;
    t.w = (sc * u.w - corr * mv.w) * g;
    const float t0s = (t0p - corr * (m0 + 1.0f)) * g;  // component 0 (scalar)

    // transport origin -> beta
    float db = bv.x * t.x + bv.y * t.y + bv.z * t.z + bv.w * t.w;
    db = wred(db);
    const float lb = db - 2.0f * b0 * t0s;        // linner(beta, t)
    const float coef = lb / (1.0f + b0);
    float4 t2;
    t2.x = t.x + coef * (bv.x + (lane == 0 ? 1.0f : 0.0f));
    t2.y = t.y + coef * bv.y;
    t2.z = t.z + coef * bv.z;
    t2.w = t.w + coef * bv.w;
    const float t20 = t0s + coef * (b0 + 1.0f);

    // expmap at beta
    float n2 = t2.x * t2.x + t2.y * t2.y + t2.z * t2.z + t2.w * t2.w;
    n2 = wred(n2);
    const float ln = n2 - 2.0f * t20 * t20;       // linner(t2, t2)
    const float nu = sqrtf(fmaxf(ln, CLAMPV));
    const float ch = coshf(nu);
    const float sn = sinhf(nu) / nu;

    float4 o;
    o.x = ch * bv.x + sn * t2.x;
    o.y = ch * bv.y + sn * t2.y;
    o.z = ch * bv.z + sn * t2.z;
    o.w = ch * bv.w + sn * t2.w;
    ((float4*)(out + (size_t)pt * CH))[lane] = o;
}

// ---------------------------------------------------------------------------
extern "C" void kernel_launch(void* const* d_in, const int* in_sizes, int n_in,
                              void* d_out, int out_size) {
    // robust input mapping by element count
    const float* x = nullptr;
    const float* beta = nullptr;
    const float* gamma = nullptr;
    for (int i = 0; i < n_in; i++) {
        if (in_sizes[i] == BSZ * NPTS * CH)      x = (const float*)d_in[i];
        else if (in_sizes[i] == CH)              beta = (const float*)d_in[i];
        else if (in_sizes[i] == 1)               gamma = (const float*)d_in[i];
    }
    float* out = (float*)d_out;

    kmean_part<<<dim3(BSZ, SM_SL), CH>>>(x);
    kmean_fin<<<BSZ, CH>>>();
    kvar_part<<<dim3(BSZ, SV_SL), 256>>>(x);
    kvar_fin<<<1, BSZ>>>(gamma);
    kfinal<<<BSZ * (NPTS / 8), 256>>>(x, beta, out);
}

// round 7
// speedup vs baseline: 1.1790x; 1.1790x over previous
#include <cuda_runtime.h>
#include <math.h>

#define BSZ   64
#define NPTS  4096            // 64*64 points per batch
#define CH    128
#define SM_SL 32              // mean slices per batch
#define SV_SL 32              // var slices per batch
#define EPSV   1e-5f
#define CLAMPV 1e-8f
#define FULLM  0xffffffffu

// ---- static scratch (no runtime allocation allowed) ----
__device__ float g_part_mean[BSZ * SM_SL * CH];   // 1 MB
__device__ float g_mean[BSZ * CH];
__device__ float g_vpart[BSZ * SV_SL];

__device__ __forceinline__ float wred(float v) {
#pragma unroll
    for (int o = 16; o > 0; o >>= 1)
        v += __shfl_xor_sync(FULLM, v, o);
    return v;
}
__device__ __forceinline__ float dot4(float4 a, float4 b) {
    return a.x * b.x + a.y * b.y + a.z * b.z + a.w * b.w;
}

// ---------------------------------------------------------------------------
// K1: per-(batch, slice) component-wise partial sums of x. Coalesced.
// ---------------------------------------------------------------------------
__global__ void kmean_part(const float* __restrict__ x) {
    const int b = blockIdx.x, s = blockIdx.y;
    const int j = threadIdx.x;                    // 0..127
    const int PPC = NPTS / SM_SL;                 // 128 points
    const float* base = x + ((size_t)b * NPTS + (size_t)s * PPC) * CH + j;
    float acc0 = 0.f, acc1 = 0.f;
#pragma unroll 16
    for (int p = 0; p < PPC; p += 2) {
        acc0 += base[(size_t)p * CH];
        acc1 += base[(size_t)(p + 1) * CH];
    }
    g_part_mean[(b * SM_SL + s) * CH + j] = acc0 + acc1;
}

// ---------------------------------------------------------------------------
// K2: finalize mean per-CTA (redundant, L2-resident), then Frechet-variance
// partials using the identity ||logmap_mean(x)||_origin = arccosh(alpha):
// exactly ONE butterfly reduction per point.
// Slice-0 CTA of each batch also publishes g_mean for K3.
// ---------------------------------------------------------------------------
__global__ void kvar_part(const float* __restrict__ x) {
    const int b = blockIdx.x, s = blockIdx.y;
    const int tid = threadIdx.x;                  // 0..255
    const int lane = tid & 31, w = tid >> 5;

    __shared__ float smean[CH];
    __shared__ float red4[4];
    __shared__ float s_inv;
    __shared__ float wsum[8];

    // reduce the 32 partials -> Euclidean mean (threads 0..127)
    float m = 0.f;
    if (tid < CH) {
#pragma unroll
        for (int sl = 0; sl < SM_SL; sl++)
            m += g_part_mean[(b * SM_SL + sl) * CH + tid];
        m *= (1.0f / (float)NPTS);
    }
    float sq = (tid < CH) ? m * m : 0.f;
    sq = wred(sq);
    if (tid < CH && lane == 0) red4[w] = sq;
    __syncthreads();
    if (tid == 0) {
        float tot = red4[0] + red4[1] + red4[2] + red4[3];
        float l = tot - 2.0f * m * m;             // linner(m,m); thread0's m = m0
        s_inv = rsqrtf(fmaxf(-l, CLAMPV));
    }
    __syncthreads();
    if (tid < CH) {
        float pm = m * s_inv;                     // projected onto hyperboloid
        smean[tid] = pm;
        if (s == 0) g_mean[b * CH + tid] = pm;
    }
    __syncthreads();

    const float m0 = smean[0];
    const float4 mv = ((const float4*)smean)[lane];
    const float* xb = x + ((size_t)b * NPTS + (size_t)s * 128 + (size_t)w * 16) * CH;

    float acc = 0.f;
#pragma unroll
    for (int p = 0; p < 16; p += 2) {
        const float4 a0 = ((const float4*)(xb + (size_t)p * CH))[lane];
        const float4 a1 = ((const float4*)(xb + (size_t)(p + 1) * CH))[lane];
        float d0 = dot4(a0, mv);
        float d1 = dot4(a1, mv);
#pragma unroll
        for (int o = 16; o > 0; o >>= 1) {        // interleaved butterflies
            d0 += __shfl_xor_sync(FULLM, d0, o);
            d1 += __shfl_xor_sync(FULLM, d1, o);
        }
        const float x00 = __shfl_sync(FULLM, a0.x, 0);
        const float x01 = __shfl_sync(FULLM, a1.x, 0);
        const float al0 = fmaxf(2.0f * m0 * x00 - d0, 1.0f + 1e-7f);
        const float al1 = fmaxf(2.0f * m0 * x01 - d1, 1.0f + 1e-7f);
        acc += acoshf(al0) + acoshf(al1);
    }
    if (lane == 0) wsum[w] = acc;
    __syncthreads();
    if (tid == 0) {
        float t = 0.f;
#pragma unroll
        for (int i = 0; i < 8; i++) t += wsum[i];
        g_vpart[b * SV_SL + s] = t;
    }
}

// ---------------------------------------------------------------------------
// K3: finalize scale per-CTA, then per-point output. Uses:
//   linner(u,u) = alpha^2 - 1  (both x and mean on the hyperboloid)
//   nu          = g * arccosh(alpha)   (transport is a Lorentz isometry)
//   beta == e0 => transport origin->beta is the identity (runtime-verified;
//   generic fallback kept for safety).
// 16 points/CTA; each warp handles 2 points with interleaved reductions.
// ---------------------------------------------------------------------------
__global__ void kfinal(const float* __restrict__ x,
                       const float* __restrict__ beta,
                       const float* __restrict__ gamma,
                       float* __restrict__ out) {
    const int b = blockIdx.x >> 8;                // 4096/16 = 256 CTAs per batch
    const int tid = threadIdx.x;                  // 0..255
    const int lane = tid & 31, w = tid >> 5;

    __shared__ float smean[CH];
    __shared__ float sbeta[CH];
    __shared__ float s_scale;

    if (tid < CH) smean[tid] = g_mean[b * CH + tid];
    else          sbeta[tid - CH] = beta[tid - CH];
    __syncthreads();

    if (tid < 32) {
        float v = wred(g_vpart[b * SV_SL + tid]);
        if (tid == 0) s_scale = gamma[0] / (v * (1.0f / (float)NPTS) + EPSV);
    }
    int ok = 1;
    if (tid < CH) ok = (sbeta[tid] == ((tid == 0) ? 1.0f : 0.0f)) ? 1 : 0;
    const int cnt = __syncthreads_count(ok);      // also orders s_scale
    const bool is_e0 = (cnt == 256);

    const float m0 = smean[0];
    const float b0 = sbeta[0];
    const float g = s_scale;
    const float4 mv = ((const float4*)smean)[lane];
    const float4 bv = ((const float4*)sbeta)[lane];

    const size_t pt = (size_t)blockIdx.x * 16 + (size_t)w * 2;
    const float4 a0 = ((const float4*)(x + pt * CH))[lane];
    const float4 a1 = ((const float4*)(x + (pt + 1) * CH))[lane];

    float d0 = dot4(a0, mv);
    float d1 = dot4(a1, mv);
#pragma unroll
    for (int o = 16; o > 0; o >>= 1) {
        d0 += __shfl_xor_sync(FULLM, d0, o);
        d1 += __shfl_xor_sync(FULLM, d1, o);
    }
    const float x00 = __shfl_sync(FULLM, a0.x, 0);
    const float x01 = __shfl_sync(FULLM, a1.x, 0);
    const float al0 = fmaxf(2.0f * m0 * x00 - d0, 1.0f + 1e-7f);
    const float al1 = fmaxf(2.0f * m0 * x01 - d1, 1.0f + 1e-7f);

#pragma unroll
    for (int q = 0; q < 2; q++) {
        const float alpha = q ? al1 : al0;
        const float x0 = q ? x01 : x00;
        const float4 xv = q ? a1 : a0;

        const float ach = acoshf(alpha);
        const float un = sqrtf(fmaxf(alpha * alpha - 1.0f, CLAMPV));
        const float sc = ach / un;
        const float u0 = x0 - alpha * m0;
        const float corr = sc * u0 / (1.0f + m0);

        // scaled tangent at origin (component 0 exactly 0)
        float4 t;
        t.x = g * (sc * (xv.x - alpha * mv.x) - corr * mv.x);
        t.y = g * (sc * (xv.y - alpha * mv.y) - corr * mv.y);
        t.z = g * (sc * (xv.z - alpha * mv.z) - corr * mv.z);
        t.w = g * (sc * (xv.w - alpha * mv.w) - corr * mv.w);
        if (lane == 0) t.x = 0.0f;

        float4 o4;
        if (is_e0) {
            // transport to beta=e0 is the identity; nu = g*acosh(alpha)
            const float nu = fmaxf(g * ach, 1e-4f);
            const float chh = coshf(nu);
            const float snc = sinhf(nu) / nu;
            o4.x = chh * bv.x + snc * t.x;        // lane0: cosh(nu)*1 + 0
            o4.y = chh * bv.y + snc * t.y;
            o4.z = chh * bv.z + snc * t.z;
            o4.w = chh * bv.w + snc * t.w;
        } else {
            // generic fallback (never runs for this problem's inputs)
            float db = wred(dot4(bv, t));         // linner(beta,t), t0=0
            const float coef = db / (1.0f + b0);
            float4 t2;
            t2.x = t.x + coef * (bv.x + ((lane == 0) ? 1.0f : 0.0f));
            t2.y = t.y + coef * bv.y;
            t2.z = t.z + coef * bv.z;
            t2.w = t.w + coef * bv.w;
            const float t20 = coef * (b0 + 1.0f);
            float n2 = wred(dot4(t2, t2));
            const float ln = n2 - 2.0f * t20 * t20;
            const float nu = sqrtf(fmaxf(ln, CLAMPV));
            const float chh = coshf(nu);
            const float snc = sinhf(nu) / nu;
            o4.x = chh * bv.x + snc * t2.x;
            o4.y = chh * bv.y + snc * t2.y;
            o4.z = chh * bv.z + snc * t2.z;
            o4.w = chh * bv.w + snc * t2.w;
        }
        ((float4*)(out + (pt + q) * CH))[lane] = o4;
    }
}

// ---------------------------------------------------------------------------
extern "C" void kernel_launch(void* const* d_in, const int* in_sizes, int n_in,
                              void* d_out, int out_size) {
    const float* x = nullptr;
    const float* beta = nullptr;
    const float* gamma = nullptr;
    for (int i = 0; i < n_in; i++) {
        if (in_sizes[i] == BSZ * NPTS * CH)      x = (const float*)d_in[i];
        else if (in_sizes[i] == CH)              beta = (const float*)d_in[i];
        else if (in_sizes[i] == 1)               gamma = (const float*)d_in[i];
    }
    float* out = (float*)d_out;

    kmean_part<<<dim3(BSZ, SM_SL), CH>>>(x);
    kvar_part<<<dim3(BSZ, SV_SL), 256>>>(x);
    kfinal<<<BSZ * (NPTS / 16), 256>>>(x, beta, gamma, out);
}